// round 11
// baseline (speedup 1.0000x reference)
#include <cuda_runtime.h>
#include <cstdint>

#define B_SZ 4
#define S_LEN 2048
#define D_MOD 1024
#define H_CNT 16
#define HD 64

// Scratch (allocation-free rule: __device__ globals)
__device__ float g_qkv[(size_t)B_SZ * S_LEN * 3 * D_MOD];   // [B*S, 3D]
__device__ float g_att[(size_t)B_SZ * S_LEN * D_MOD];       // [B*S, D]

// ---------------------------------------------------------------------------
// tf32 helpers
// ---------------------------------------------------------------------------
__device__ __forceinline__ uint32_t f2tf32(float x) {
    uint32_t r;
    asm("cvt.rna.tf32.f32 %0, %1;" : "=r"(r) : "f"(x));
    return r;
}
__device__ __forceinline__ float2 splitf2(float x) {
    float hi = __uint_as_float(f2tf32(x));
    float lo = __uint_as_float(f2tf32(x - hi));
    return make_float2(hi, lo);
}
// D += A(16x8) * B(8x8), tf32, fp32 accum
__device__ __forceinline__ void mma8(float* c, const float* a, const float* b) {
    asm volatile(
        "mma.sync.aligned.m16n8k8.row.col.f32.tf32.tf32.f32 "
        "{%0,%1,%2,%3}, {%4,%5,%6,%7}, {%8,%9}, {%0,%1,%2,%3};"
        : "+f"(c[0]), "+f"(c[1]), "+f"(c[2]), "+f"(c[3])
        : "r"(__float_as_uint(a[0])), "r"(__float_as_uint(a[1])),
          "r"(__float_as_uint(a[2])), "r"(__float_as_uint(a[3])),
          "r"(__float_as_uint(b[0])), "r"(__float_as_uint(b[1])));
}

// ---------------------------------------------------------------------------
// GEMM: C = A*B, split-tf32, pipelined. 128x128x16 tile, 256 thr,
// 8 warps 2(M)x4(N). Ping-pong packed-float2 smem (dynamic):
//   sA[buf] [m][k] stride 18, sB[buf] [k][n] stride 132.
// Per iter: split/STS(prefetched regs) -> 1 sync -> LDG next -> mma.
// ---------------------------------------------------------------------------
#define BM 128
#define BN 128
#define BK 16
#define AS2 18
#define BS2 132
#define SA_SZ (BM * AS2)
#define SB_SZ (BK * BS2)

extern __shared__ float2 gsm[];

__global__ __launch_bounds__(256, 2) void gemm_tf32(
    const float* __restrict__ A, const float* __restrict__ B,
    float* __restrict__ C, int M, int N, int K)
{
    const int tid = threadIdx.x;
    const int lane = tid & 31, warp = tid >> 5;
    const int wm = warp & 1, wn = warp >> 1;
    const int g = lane >> 2, t = lane & 3;
    const int m0 = blockIdx.y * BM, n0 = blockIdx.x * BN;

    const int ar = tid >> 2;            // 0..63
    const int ac = (tid & 3) * 4;       // 0,4,8,12
    const int br = tid >> 5;            // 0..7
    const int bc = (tid & 31) * 4;      // 0..124

    float acc[4][4][4];
    #pragma unroll
    for (int i = 0; i < 4; i++)
        #pragma unroll
        for (int j = 0; j < 4; j++)
            #pragma unroll
            for (int e = 0; e < 4; e++) acc[i][j][e] = 0.0f;

    // prefetch tile 0
    float4 pa[2], pb[2];
    #pragma unroll
    for (int p = 0; p < 2; p++) {
        pa[p] = *(const float4*)(A + (size_t)(m0 + ar + 64 * p) * K + ac);
        pb[p] = *(const float4*)(B + (size_t)(br + 8 * p) * N + n0 + bc);
    }

    const int nk = K / BK;
    for (int kt = 0; kt < nk; kt++) {
        float2* sA = gsm + (kt & 1) * SA_SZ;
        float2* sB = gsm + 2 * SA_SZ + (kt & 1) * SB_SZ;

        // split + store prefetched tile
        #pragma unroll
        for (int p = 0; p < 2; p++) {
            int row = ar + 64 * p;
            float2 e0 = splitf2(pa[p].x), e1 = splitf2(pa[p].y);
            float2 e2 = splitf2(pa[p].z), e3 = splitf2(pa[p].w);
            *(float4*)&sA[row * AS2 + ac]     = make_float4(e0.x, e0.y, e1.x, e1.y);
            *(float4*)&sA[row * AS2 + ac + 2] = make_float4(e2.x, e2.y, e3.x, e3.y);
            int rowb = br + 8 * p;
            e0 = splitf2(pb[p].x); e1 = splitf2(pb[p].y);
            e2 = splitf2(pb[p].z); e3 = splitf2(pb[p].w);
            *(float4*)&sB[rowb * BS2 + bc]     = make_float4(e0.x, e0.y, e1.x, e1.y);
            *(float4*)&sB[rowb * BS2 + bc + 2] = make_float4(e2.x, e2.y, e3.x, e3.y);
        }
        __syncthreads();

        // prefetch next tile (latency hidden behind mma phase)
        if (kt + 1 < nk) {
            int k0 = (kt + 1) * BK;
            #pragma unroll
            for (int p = 0; p < 2; p++) {
                pa[p] = *(const float4*)(A + (size_t)(m0 + ar + 64 * p) * K + k0 + ac);
                pb[p] = *(const float4*)(B + (size_t)(k0 + br + 8 * p) * N + n0 + bc);
            }
        }

        // compute
        #pragma unroll
        for (int ks = 0; ks < 2; ks++) {
            const int kb = ks * 8;
            float2 af[4][4], bf[4][2];
            #pragma unroll
            for (int mt = 0; mt < 4; mt++) {
                int mb = wm * 64 + mt * 16;
                af[mt][0] = sA[(mb + g) * AS2 + kb + t];
                af[mt][1] = sA[(mb + g + 8) * AS2 + kb + t];
                af[mt][2] = sA[(mb + g) * AS2 + kb + t + 4];
                af[mt][3] = sA[(mb + g + 8) * AS2 + kb + t + 4];
            }
            #pragma unroll
            for (int nt = 0; nt < 4; nt++) {
                int nb = wn * 32 + nt * 8;
                bf[nt][0] = sB[(kb + t) * BS2 + nb + g];
                bf[nt][1] = sB[(kb + t + 4) * BS2 + nb + g];
            }
            #pragma unroll
            for (int mt = 0; mt < 4; mt++) {
                float ahi[4] = {af[mt][0].x, af[mt][1].x, af[mt][2].x, af[mt][3].x};
                float alo[4] = {af[mt][0].y, af[mt][1].y, af[mt][2].y, af[mt][3].y};
                #pragma unroll
                for (int nt = 0; nt < 4; nt++) {
                    float bhi[2] = {bf[nt][0].x, bf[nt][1].x};
                    float blo[2] = {bf[nt][0].y, bf[nt][1].y};
                    mma8(acc[mt][nt], ahi, bhi);
                    mma8(acc[mt][nt], ahi, blo);
                    mma8(acc[mt][nt], alo, bhi);
                }
            }
        }
        // no trailing sync: next iter writes the other buffer (see hazard note)
    }

    #pragma unroll
    for (int mt = 0; mt < 4; mt++) {
        int row = m0 + wm * 64 + mt * 16 + g;
        #pragma unroll
        for (int nt = 0; nt < 4; nt++) {
            int col = n0 + wn * 32 + nt * 8 + 2 * t;
            *(float2*)(C + (size_t)row * N + col) =
                make_float2(acc[mt][nt][0], acc[mt][nt][1]);
            *(float2*)(C + (size_t)(row + 8) * N + col) =
                make_float2(acc[mt][nt][2], acc[mt][nt][3]);
        }
    }
}

// ---------------------------------------------------------------------------
// Flash attention, split-tf32, pipelined. Block = (b, h, 256-query tile),
// 512 threads, 16 warps x 16 q rows. K/V tiles: 64 keys.
// smem packed float2, stride QS2=68: sQ 256x68, sK 64x68, sV 64x68.
// Per iter: sync, split/STS(prefetched), sync, LDG next (hidden), compute.
// P stays in registers (C-frag -> A-frag shfl transpose).
// ---------------------------------------------------------------------------
#define QS2 68

__global__ __launch_bounds__(512, 1) void attn_tf32()
{
    extern __shared__ float2 smf2[];
    float2* sQ = smf2;                  // 256*68
    float2* sK = sQ + 256 * QS2;        // 64*68
    float2* sV = sK + 64 * QS2;         // 64*68

    const int tid = threadIdx.x;
    const int lane = tid & 31, warp = tid >> 5;
    const int g = lane >> 2, t = lane & 3;
    const int b = blockIdx.y >> 4, h = blockIdx.y & 15;
    const int q0 = blockIdx.x * 256;
    const int mq = warp * 16;
    const size_t rstr = 3 * D_MOD;
    const float* base = g_qkv + (size_t)b * S_LEN * rstr + h * HD;

    // ---- stage Q: load, scale, split, store packed ----
    {
        const int c4 = tid & 15, r0 = tid >> 4;
        #pragma unroll
        for (int p = 0; p < 8; p++) {
            int r = r0 + p * 32;
            float4 v = *(const float4*)(base + (size_t)(q0 + r) * rstr + 4 * c4);
            float2 e0 = splitf2(v.x * 0.125f), e1 = splitf2(v.y * 0.125f);
            float2 e2 = splitf2(v.z * 0.125f), e3 = splitf2(v.w * 0.125f);
            *(float4*)&sQ[r * QS2 + 4 * c4]     = make_float4(e0.x, e0.y, e1.x, e1.y);
            *(float4*)&sQ[r * QS2 + 4 * c4 + 2] = make_float4(e2.x, e2.y, e3.x, e3.y);
        }
    }

    const int c4 = tid & 15, j0 = tid >> 4;   // loader mapping
    // ---- prefetch K/V tile 0 ----
    float4 pk[2], pv[2];
    #pragma unroll
    for (int p = 0; p < 2; p++) {
        const float* kb_ = base + (size_t)(j0 + p * 32) * rstr + 4 * c4;
        pk[p] = *(const float4*)(kb_ + D_MOD);
        pv[p] = *(const float4*)(kb_ + 2 * D_MOD);
    }

    float o[8][4];
    #pragma unroll
    for (int i = 0; i < 8; i++)
        #pragma unroll
        for (int e = 0; e < 4; e++) o[i][e] = 0.0f;
    float m0r = -1e30f, m1r = -1e30f, l0 = 0.0f, l1 = 0.0f;

    // shuffle constants for C-frag -> A-frag (P) conversion
    const int ls1 = (lane & ~3) + (t >> 1);
    const int ls2 = ls1 + 2;
    const bool odd = (t & 1);

    for (int kt = 0; kt < S_LEN / 64; kt++) {
        __syncthreads();   // iter0: sQ staged; else: prior mma done with sK/sV
        // ---- split + store prefetched K/V ----
        #pragma unroll
        for (int p = 0; p < 2; p++) {
            int j = j0 + p * 32;
            float2 e0 = splitf2(pk[p].x), e1 = splitf2(pk[p].y);
            float2 e2 = splitf2(pk[p].z), e3 = splitf2(pk[p].w);
            *(float4*)&sK[j * QS2 + 4 * c4]     = make_float4(e0.x, e0.y, e1.x, e1.y);
            *(float4*)&sK[j * QS2 + 4 * c4 + 2] = make_float4(e2.x, e2.y, e3.x, e3.y);
            e0 = splitf2(pv[p].x); e1 = splitf2(pv[p].y);
            e2 = splitf2(pv[p].z); e3 = splitf2(pv[p].w);
            *(float4*)&sV[j * QS2 + 4 * c4]     = make_float4(e0.x, e0.y, e1.x, e1.y);
            *(float4*)&sV[j * QS2 + 4 * c4 + 2] = make_float4(e2.x, e2.y, e3.x, e3.y);
        }
        __syncthreads();

        // ---- prefetch next K/V tile (hidden behind compute) ----
        if (kt + 1 < S_LEN / 64) {
            #pragma unroll
            for (int p = 0; p < 2; p++) {
                const float* kb_ = base + (size_t)((kt + 1) * 64 + j0 + p * 32) * rstr + 4 * c4;
                pk[p] = *(const float4*)(kb_ + D_MOD);
                pv[p] = *(const float4*)(kb_ + 2 * D_MOD);
            }
        }

        // ---- S = Q K^T ----
        float s[8][4];
        #pragma unroll
        for (int i = 0; i < 8; i++)
            #pragma unroll
            for (int e = 0; e < 4; e++) s[i][e] = 0.0f;

        #pragma unroll
        for (int ds = 0; ds < 8; ds++) {
            int kb = ds * 8;
            float2 q0f = sQ[(mq + g) * QS2 + kb + t];
            float2 q1f = sQ[(mq + g + 8) * QS2 + kb + t];
            float2 q2f = sQ[(mq + g) * QS2 + kb + t + 4];
            float2 q3f = sQ[(mq + g + 8) * QS2 + kb + t + 4];
            float qhi[4] = {q0f.x, q1f.x, q2f.x, q3f.x};
            float qlo[4] = {q0f.y, q1f.y, q2f.y, q3f.y};
            #pragma unroll
            for (int nt = 0; nt < 8; nt++) {
                float2 k0f = sK[(nt * 8 + g) * QS2 + kb + t];
                float2 k1f = sK[(nt * 8 + g) * QS2 + kb + t + 4];
                float bhi[2] = {k0f.x, k1f.x};
                float blo[2] = {k0f.y, k1f.y};
                mma8(s[nt], qhi, bhi);
                mma8(s[nt], qhi, blo);
                mma8(s[nt], qlo, bhi);
            }
        }

        // ---- online softmax (rows g, g+8) ----
        float mx0 = -1e30f, mx1 = -1e30f;
        #pragma unroll
        for (int nt = 0; nt < 8; nt++) {
            mx0 = fmaxf(mx0, fmaxf(s[nt][0], s[nt][1]));
            mx1 = fmaxf(mx1, fmaxf(s[nt][2], s[nt][3]));
        }
        mx0 = fmaxf(mx0, __shfl_xor_sync(0xffffffffu, mx0, 1));
        mx0 = fmaxf(mx0, __shfl_xor_sync(0xffffffffu, mx0, 2));
        mx1 = fmaxf(mx1, __shfl_xor_sync(0xffffffffu, mx1, 1));
        mx1 = fmaxf(mx1, __shfl_xor_sync(0xffffffffu, mx1, 2));

        float mn0 = fmaxf(m0r, mx0), mn1 = fmaxf(m1r, mx1);
        float f0 = __expf(m0r - mn0), f1 = __expf(m1r - mn1);
        m0r = mn0; m1r = mn1;

        float rs0 = 0.0f, rs1 = 0.0f;
        #pragma unroll
        for (int nt = 0; nt < 8; nt++) {
            s[nt][0] = __expf(s[nt][0] - mn0); rs0 += s[nt][0];
            s[nt][1] = __expf(s[nt][1] - mn0); rs0 += s[nt][1];
            s[nt][2] = __expf(s[nt][2] - mn1); rs1 += s[nt][2];
            s[nt][3] = __expf(s[nt][3] - mn1); rs1 += s[nt][3];
        }
        rs0 += __shfl_xor_sync(0xffffffffu, rs0, 1);
        rs0 += __shfl_xor_sync(0xffffffffu, rs0, 2);
        rs1 += __shfl_xor_sync(0xffffffffu, rs1, 1);
        rs1 += __shfl_xor_sync(0xffffffffu, rs1, 2);
        l0 = l0 * f0 + rs0;
        l1 = l1 * f1 + rs1;
        #pragma unroll
        for (int nt = 0; nt < 8; nt++) {
            o[nt][0] *= f0; o[nt][1] *= f0;
            o[nt][2] *= f1; o[nt][3] *= f1;
        }

        // ---- O += P V : P C-frag -> A-frag via shfl, V from smem ----
        #pragma unroll
        for (int ks = 0; ks < 8; ks++) {
            float p00 = __shfl_sync(0xffffffffu, s[ks][0], ls1);
            float p01 = __shfl_sync(0xffffffffu, s[ks][1], ls1);
            float p10 = __shfl_sync(0xffffffffu, s[ks][2], ls1);
            float p11 = __shfl_sync(0xffffffffu, s[ks][3], ls1);
            float p20 = __shfl_sync(0xffffffffu, s[ks][0], ls2);
            float p21 = __shfl_sync(0xffffffffu, s[ks][1], ls2);
            float p30 = __shfl_sync(0xffffffffu, s[ks][2], ls2);
            float p31 = __shfl_sync(0xffffffffu, s[ks][3], ls2);
            float2 A0 = splitf2(odd ? p01 : p00);   // (g,    kb+t)
            float2 A1 = splitf2(odd ? p11 : p10);   // (g+8,  kb+t)
            float2 A2 = splitf2(odd ? p21 : p20);   // (g,    kb+t+4)
            float2 A3 = splitf2(odd ? p31 : p30);   // (g+8,  kb+t+4)
            float ahi[4] = {A0.x, A1.x, A2.x, A3.x};
            float alo[4] = {A0.y, A1.y, A2.y, A3.y};
            int kb = ks * 8;
            #pragma unroll
            for (int nt = 0; nt < 8; nt++) {
                float2 v0f = sV[(kb + t) * QS2 + nt * 8 + g];
                float2 v1f = sV[(kb + t + 4) * QS2 + nt * 8 + g];
                float bhi[2] = {v0f.x, v1f.x};
                float blo[2] = {v0f.y, v1f.y};
                mma8(o[nt], ahi, bhi);
                mma8(o[nt], ahi, blo);
                mma8(o[nt], alo, bhi);
            }
        }
    }

    // ---- epilogue ----
    float inv0 = 1.0f / l0, inv1 = 1.0f / l1;
    float* ob = g_att + ((size_t)b * S_LEN + q0 + mq) * D_MOD + h * HD;
    #pragma unroll
    for (int nt = 0; nt < 8; nt++) {
        int col = nt * 8 + 2 * t;
        *(float2*)(ob + (size_t)g * D_MOD + col) =
            make_float2(o[nt][0] * inv0, o[nt][1] * inv0);
        *(float2*)(ob + (size_t)(g + 8) * D_MOD + col) =
            make_float2(o[nt][2] * inv1, o[nt][3] * inv1);
    }
}

// ---------------------------------------------------------------------------
extern "C" void kernel_launch(void* const* d_in, const int* in_sizes, int n_in,
                              void* d_out, int out_size)
{
    const float* x = nullptr;
    const float* w_qkv = nullptr;
    const float* w_out = nullptr;
    for (int i = 0; i < n_in; i++) {
        if (in_sizes[i] == B_SZ * S_LEN * D_MOD) x = (const float*)d_in[i];
        else if (in_sizes[i] == D_MOD * 3 * D_MOD) w_qkv = (const float*)d_in[i];
        else if (in_sizes[i] == D_MOD * D_MOD) w_out = (const float*)d_in[i];
    }
    float* out = (float*)d_out;

    float* qkv_p = nullptr;
    float* att_p = nullptr;
    cudaGetSymbolAddress((void**)&qkv_p, g_qkv);
    cudaGetSymbolAddress((void**)&att_p, g_att);

    // GEMM smem: 2 ping-pong buffers of (sA + sB) packed float2
    const int gemm_smem = 2 * (SA_SZ + SB_SZ) * (int)sizeof(float2);  // 70656
    cudaFuncSetAttribute(gemm_tf32, cudaFuncAttributeMaxDynamicSharedMemorySize, gemm_smem);

    // Attention smem: sQ 256 + sK 64 + sV 64 rows, stride 68 float2
    const int attn_smem = (256 + 64 + 64) * QS2 * (int)sizeof(float2); // 208896
    cudaFuncSetAttribute(attn_tf32, cudaFuncAttributeMaxDynamicSharedMemorySize, attn_smem);

    // 1) QKV projection: [8192,1024] x [1024,3072]
    gemm_tf32<<<dim3(3 * D_MOD / BN, B_SZ * S_LEN / BM), dim3(256), gemm_smem>>>(
        x, w_qkv, qkv_p, B_SZ * S_LEN, 3 * D_MOD, D_MOD);

    // 2) Attention: (b,h) x 256-query tiles
    attn_tf32<<<dim3(S_LEN / 256, B_SZ * H_CNT), dim3(512), attn_smem>>>();

    // 3) Output projection: [8192,1024] x [1024,1024]
    gemm_tf32<<<dim3(D_MOD / BN, B_SZ * S_LEN / BM), dim3(256), gemm_smem>>>(
        att_p, w_out, out, B_SZ * S_LEN, D_MOD, D_MOD);
}

// round 12
// speedup vs baseline: 1.0670x; 1.0670x over previous
#include <cuda_runtime.h>
#include <cstdint>

#define B_SZ 4
#define S_LEN 2048
#define D_MOD 1024
#define H_CNT 16
#define HD 64
#define MROWS (B_SZ * S_LEN)          // 8192

// ---------------------------------------------------------------------------
// Packed (hi,lo) scratch in global memory (allocation-free rule)
// ---------------------------------------------------------------------------
__device__ float2 g_qkvp[(size_t)MROWS * 3 * D_MOD];  // split qkv (Q pre-scaled)
__device__ float2 g_attp[(size_t)MROWS * D_MOD];      // split attention output
__device__ float2 ps_x[(size_t)MROWS * D_MOD];        // split x
__device__ float2 ps_wqkv[(size_t)D_MOD * 3 * D_MOD]; // split w_qkv
__device__ float2 ps_wout[(size_t)D_MOD * D_MOD];     // split w_out

// ---------------------------------------------------------------------------
// tf32 helpers
// ---------------------------------------------------------------------------
__device__ __forceinline__ uint32_t f2tf32(float x) {
    uint32_t r;
    asm("cvt.rna.tf32.f32 %0, %1;" : "=r"(r) : "f"(x));
    return r;
}
__device__ __forceinline__ float2 splitf2(float x) {
    float hi = __uint_as_float(f2tf32(x));
    float lo = __uint_as_float(f2tf32(x - hi));
    return make_float2(hi, lo);
}
__device__ __forceinline__ void mma8(float* c, const float* a, const float* b) {
    asm volatile(
        "mma.sync.aligned.m16n8k8.row.col.f32.tf32.tf32.f32 "
        "{%0,%1,%2,%3}, {%4,%5,%6,%7}, {%8,%9}, {%0,%1,%2,%3};"
        : "+f"(c[0]), "+f"(c[1]), "+f"(c[2]), "+f"(c[3])
        : "r"(__float_as_uint(a[0])), "r"(__float_as_uint(a[1])),
          "r"(__float_as_uint(a[2])), "r"(__float_as_uint(a[3])),
          "r"(__float_as_uint(b[0])), "r"(__float_as_uint(b[1])));
}

// cp.async helpers (16B)
__device__ __forceinline__ void cpa16(void* sdst, const void* gsrc) {
    uint32_t s = (uint32_t)__cvta_generic_to_shared(sdst);
    asm volatile("cp.async.cg.shared.global [%0], [%1], 16;" :: "r"(s), "l"(gsrc));
}
__device__ __forceinline__ void cpa_commit() {
    asm volatile("cp.async.commit_group;");
}
template <int N>
__device__ __forceinline__ void cpa_wait() {
    asm volatile("cp.async.wait_group %0;" :: "n"(N));
}

// ---------------------------------------------------------------------------
// Prep: elementwise split fp32 -> packed float2 (vectorized)
// ---------------------------------------------------------------------------
__global__ void presplit(const float* __restrict__ in, float2* __restrict__ out, int n4)
{
    int i = blockIdx.x * blockDim.x + threadIdx.x;
    if (i >= n4) return;
    float4 v = ((const float4*)in)[i];
    float2 e0 = splitf2(v.x), e1 = splitf2(v.y);
    float2 e2 = splitf2(v.z), e3 = splitf2(v.w);
    float4* o = (float4*)(out + (size_t)i * 4);
    o[0] = make_float4(e0.x, e0.y, e1.x, e1.y);
    o[1] = make_float4(e2.x, e2.y, e3.x, e3.y);
}

// ---------------------------------------------------------------------------
// GEMM on pre-split operands: C = A*B. 128x128x16 tile, 256 thr, 8 warps.
// cp.async double-buffered smem, no in-loop conversion.
// Epilogue: plain fp32 (Cout) or split-packed (Cpack, with per-block scale
// 0.125 for cols < scale_below — Q columns of the qkv projection).
// ---------------------------------------------------------------------------
#define BM 128
#define BN 128
#define BK 16
#define AS2 18
#define BS2 132
#define SA_SZ (BM * AS2)
#define SB_SZ (BK * BS2)

extern __shared__ float2 gsm[];

__global__ __launch_bounds__(256, 2) void gemm_ps(
    const float2* __restrict__ A, const float2* __restrict__ B,
    float* __restrict__ Cout, float2* __restrict__ Cpack,
    int M, int N, int K, int scale_below)
{
    const int tid = threadIdx.x;
    const int lane = tid & 31, warp = tid >> 5;
    const int wm = warp & 1, wn = warp >> 1;
    const int g = lane >> 2, t = lane & 3;
    const int m0 = blockIdx.y * BM, n0 = blockIdx.x * BN;

    float acc[4][4][4];
    #pragma unroll
    for (int i = 0; i < 4; i++)
        #pragma unroll
        for (int j = 0; j < 4; j++)
            #pragma unroll
            for (int e = 0; e < 4; e++) acc[i][j][e] = 0.0f;

    // chunk mappings (16B = 2 packed elements)
    // A tile: 128 rows x 8 k-chunks = 1024 chunks; B tile: 16 rows x 64 n-chunks
    const int nk = K / BK;

    auto issue_tile = [&](int kt, int buf) {
        float2* sA = gsm + buf * SA_SZ;
        float2* sB = gsm + 2 * SA_SZ + buf * SB_SZ;
        int k0 = kt * BK;
        #pragma unroll
        for (int i = 0; i < 4; i++) {
            int c = tid + 256 * i;
            int row = c >> 3, kc = c & 7;
            cpa16(&sA[row * AS2 + 2 * kc],
                  A + (size_t)(m0 + row) * K + k0 + 2 * kc);
        }
        #pragma unroll
        for (int i = 0; i < 4; i++) {
            int c = tid + 256 * i;
            int row = c >> 6, nc = c & 63;
            cpa16(&sB[row * BS2 + 2 * nc],
                  B + (size_t)(k0 + row) * N + n0 + 2 * nc);
        }
        cpa_commit();
    };

    issue_tile(0, 0);

    for (int kt = 0; kt < nk; kt++) {
        if (kt + 1 < nk) {
            issue_tile(kt + 1, (kt + 1) & 1);
            cpa_wait<1>();
        } else {
            cpa_wait<0>();
        }
        __syncthreads();

        float2* sA = gsm + (kt & 1) * SA_SZ;
        float2* sB = gsm + 2 * SA_SZ + (kt & 1) * SB_SZ;

        #pragma unroll
        for (int ks = 0; ks < 2; ks++) {
            const int kb = ks * 8;
            float2 af[4][4], bf[4][2];
            #pragma unroll
            for (int mt = 0; mt < 4; mt++) {
                int mb = wm * 64 + mt * 16;
                af[mt][0] = sA[(mb + g) * AS2 + kb + t];
                af[mt][1] = sA[(mb + g + 8) * AS2 + kb + t];
                af[mt][2] = sA[(mb + g) * AS2 + kb + t + 4];
                af[mt][3] = sA[(mb + g + 8) * AS2 + kb + t + 4];
            }
            #pragma unroll
            for (int nt = 0; nt < 4; nt++) {
                int nb = wn * 32 + nt * 8;
                bf[nt][0] = sB[(kb + t) * BS2 + nb + g];
                bf[nt][1] = sB[(kb + t + 4) * BS2 + nb + g];
            }
            #pragma unroll
            for (int mt = 0; mt < 4; mt++) {
                float ahi[4] = {af[mt][0].x, af[mt][1].x, af[mt][2].x, af[mt][3].x};
                float alo[4] = {af[mt][0].y, af[mt][1].y, af[mt][2].y, af[mt][3].y};
                #pragma unroll
                for (int nt = 0; nt < 4; nt++) {
                    float bhi[2] = {bf[nt][0].x, bf[nt][1].x};
                    float blo[2] = {bf[nt][0].y, bf[nt][1].y};
                    mma8(acc[mt][nt], ahi, bhi);
                    mma8(acc[mt][nt], ahi, blo);
                    mma8(acc[mt][nt], alo, bhi);
                }
            }
        }
        __syncthreads();   // readers done before this buffer is rewritten
    }

    // epilogue
    const float cs = (n0 < scale_below) ? 0.125f : 1.0f;
    #pragma unroll
    for (int mt = 0; mt < 4; mt++) {
        int row = m0 + wm * 64 + mt * 16 + g;
        #pragma unroll
        for (int nt = 0; nt < 4; nt++) {
            int col = n0 + wn * 32 + nt * 8 + 2 * t;
            if (Cpack) {
                float2 e0 = splitf2(acc[mt][nt][0] * cs);
                float2 e1 = splitf2(acc[mt][nt][1] * cs);
                *(float4*)&Cpack[(size_t)row * N + col] =
                    make_float4(e0.x, e0.y, e1.x, e1.y);
                e0 = splitf2(acc[mt][nt][2] * cs);
                e1 = splitf2(acc[mt][nt][3] * cs);
                *(float4*)&Cpack[(size_t)(row + 8) * N + col] =
                    make_float4(e0.x, e0.y, e1.x, e1.y);
            } else {
                *(float2*)(Cout + (size_t)row * N + col) =
                    make_float2(acc[mt][nt][0], acc[mt][nt][1]);
                *(float2*)(Cout + (size_t)(row + 8) * N + col) =
                    make_float2(acc[mt][nt][2], acc[mt][nt][3]);
            }
        }
    }
}

// ---------------------------------------------------------------------------
// Flash attention on pre-split qkv. Block = (b, h, 256-query tile),
// 512 threads, 16 warps x 16 q rows. K/V tiles: 64 keys, cp.async staged.
// smem packed float2, stride QS2=68: sQ 256x68, sK 64x68, sV 64x68.
// P stays in registers (C-frag -> A-frag shfl transpose + split).
// Writes split output to g_attp.
// ---------------------------------------------------------------------------
#define QS2 68

__global__ __launch_bounds__(512, 1) void attn_ps()
{
    extern __shared__ float2 smf2[];
    float2* sQ = smf2;                  // 256*68
    float2* sK = sQ + 256 * QS2;        // 64*68
    float2* sV = sK + 64 * QS2;         // 64*68

    const int tid = threadIdx.x;
    const int lane = tid & 31, warp = tid >> 5;
    const int g = lane >> 2, t = lane & 3;
    const int b = blockIdx.y >> 4, h = blockIdx.y & 15;
    const int q0 = blockIdx.x * 256;
    const int mq = warp * 16;
    const float2* gq = g_qkvp + (size_t)b * S_LEN * (3 * D_MOD) + h * HD;

    // ---- stage Q via cp.async (pre-scaled + pre-split by GEMM1) ----
    // 256 rows x 32 chunks = 8192 chunks; 16 per thread
    #pragma unroll
    for (int i = 0; i < 16; i++) {
        int c = tid + 512 * i;
        int r = c >> 5, dc = c & 31;
        cpa16(&sQ[r * QS2 + 2 * dc],
              gq + (size_t)(q0 + r) * (3 * D_MOD) + 2 * dc);
    }
    cpa_commit();

    float o[8][4];
    #pragma unroll
    for (int i = 0; i < 8; i++)
        #pragma unroll
        for (int e = 0; e < 4; e++) o[i][e] = 0.0f;
    float m0r = -1e30f, m1r = -1e30f, l0 = 0.0f, l1 = 0.0f;

    const int ls1 = (lane & ~3) + (t >> 1);
    const int ls2 = ls1 + 2;
    const bool odd = (t & 1);

    for (int kt = 0; kt < S_LEN / 64; kt++) {
        __syncthreads();   // prior iter's sK/sV readers done
        // ---- stage K/V tile kt: 64 rows x 32 chunks each; 4+4 per thread ----
        #pragma unroll
        for (int i = 0; i < 4; i++) {
            int c = tid + 512 * i;
            int j = c >> 5, dc = c & 31;
            const float2* src = gq + (size_t)(kt * 64 + j) * (3 * D_MOD) + 2 * dc;
            cpa16(&sK[j * QS2 + 2 * dc], src + D_MOD);
            cpa16(&sV[j * QS2 + 2 * dc], src + 2 * D_MOD);
        }
        cpa_commit();
        cpa_wait<0>();     // iter 0 also drains the Q group
        __syncthreads();

        // ---- S = Q K^T ----
        float s[8][4];
        #pragma unroll
        for (int i = 0; i < 8; i++)
            #pragma unroll
            for (int e = 0; e < 4; e++) s[i][e] = 0.0f;

        #pragma unroll
        for (int ds = 0; ds < 8; ds++) {
            int kb = ds * 8;
            float2 q0f = sQ[(mq + g) * QS2 + kb + t];
            float2 q1f = sQ[(mq + g + 8) * QS2 + kb + t];
            float2 q2f = sQ[(mq + g) * QS2 + kb + t + 4];
            float2 q3f = sQ[(mq + g + 8) * QS2 + kb + t + 4];
            float qhi[4] = {q0f.x, q1f.x, q2f.x, q3f.x};
            float qlo[4] = {q0f.y, q1f.y, q2f.y, q3f.y};
            #pragma unroll
            for (int nt = 0; nt < 8; nt++) {
                float2 k0f = sK[(nt * 8 + g) * QS2 + kb + t];
                float2 k1f = sK[(nt * 8 + g) * QS2 + kb + t + 4];
                float bhi[2] = {k0f.x, k1f.x};
                float blo[2] = {k0f.y, k1f.y};
                mma8(s[nt], qhi, bhi);
                mma8(s[nt], qhi, blo);
                mma8(s[nt], qlo, bhi);
            }
        }

        // ---- online softmax (rows g, g+8) ----
        float mx0 = -1e30f, mx1 = -1e30f;
        #pragma unroll
        for (int nt = 0; nt < 8; nt++) {
            mx0 = fmaxf(mx0, fmaxf(s[nt][0], s[nt][1]));
            mx1 = fmaxf(mx1, fmaxf(s[nt][2], s[nt][3]));
        }
        mx0 = fmaxf(mx0, __shfl_xor_sync(0xffffffffu, mx0, 1));
        mx0 = fmaxf(mx0, __shfl_xor_sync(0xffffffffu, mx0, 2));
        mx1 = fmaxf(mx1, __shfl_xor_sync(0xffffffffu, mx1, 1));
        mx1 = fmaxf(mx1, __shfl_xor_sync(0xffffffffu, mx1, 2));

        float mn0 = fmaxf(m0r, mx0), mn1 = fmaxf(m1r, mx1);
        float f0 = __expf(m0r - mn0), f1 = __expf(m1r - mn1);
        m0r = mn0; m1r = mn1;

        float rs0 = 0.0f, rs1 = 0.0f;
        #pragma unroll
        for (int nt = 0; nt < 8; nt++) {
            s[nt][0] = __expf(s[nt][0] - mn0); rs0 += s[nt][0];
            s[nt][1] = __expf(s[nt][1] - mn0); rs0 += s[nt][1];
            s[nt][2] = __expf(s[nt][2] - mn1); rs1 += s[nt][2];
            s[nt][3] = __expf(s[nt][3] - mn1); rs1 += s[nt][3];
        }
        rs0 += __shfl_xor_sync(0xffffffffu, rs0, 1);
        rs0 += __shfl_xor_sync(0xffffffffu, rs0, 2);
        rs1 += __shfl_xor_sync(0xffffffffu, rs1, 1);
        rs1 += __shfl_xor_sync(0xffffffffu, rs1, 2);
        l0 = l0 * f0 + rs0;
        l1 = l1 * f1 + rs1;
        #pragma unroll
        for (int nt = 0; nt < 8; nt++) {
            o[nt][0] *= f0; o[nt][1] *= f0;
            o[nt][2] *= f1; o[nt][3] *= f1;
        }

        // ---- O += P V ----
        #pragma unroll
        for (int ks = 0; ks < 8; ks++) {
            float p00 = __shfl_sync(0xffffffffu, s[ks][0], ls1);
            float p01 = __shfl_sync(0xffffffffu, s[ks][1], ls1);
            float p10 = __shfl_sync(0xffffffffu, s[ks][2], ls1);
            float p11 = __shfl_sync(0xffffffffu, s[ks][3], ls1);
            float p20 = __shfl_sync(0xffffffffu, s[ks][0], ls2);
            float p21 = __shfl_sync(0xffffffffu, s[ks][1], ls2);
            float p30 = __shfl_sync(0xffffffffu, s[ks][2], ls2);
            float p31 = __shfl_sync(0xffffffffu, s[ks][3], ls2);
            float2 A0 = splitf2(odd ? p01 : p00);
            float2 A1 = splitf2(odd ? p11 : p10);
            float2 A2 = splitf2(odd ? p21 : p20);
            float2 A3 = splitf2(odd ? p31 : p30);
            float ahi[4] = {A0.x, A1.x, A2.x, A3.x};
            float alo[4] = {A0.y, A1.y, A2.y, A3.y};
            int kb = ks * 8;
            #pragma unroll
            for (int nt = 0; nt < 8; nt++) {
                float2 v0f = sV[(kb + t) * QS2 + nt * 8 + g];
                float2 v1f = sV[(kb + t + 4) * QS2 + nt * 8 + g];
                float bhi[2] = {v0f.x, v1f.x};
                float blo[2] = {v0f.y, v1f.y};
                mma8(o[nt], ahi, bhi);
                mma8(o[nt], ahi, blo);
                mma8(o[nt], alo, bhi);
            }
        }
    }

    // ---- epilogue: normalize, split, write packed [B*S, D] for GEMM2 ----
    float inv0 = 1.0f / l0, inv1 = 1.0f / l1;
    float2* ob = g_attp + ((size_t)b * S_LEN + q0 + mq) * D_MOD + h * HD;
    #pragma unroll
    for (int nt = 0; nt < 8; nt++) {
        int col = nt * 8 + 2 * t;
        float2 e0 = splitf2(o[nt][0] * inv0);
        float2 e1 = splitf2(o[nt][1] * inv0);
        *(float4*)&ob[(size_t)g * D_MOD + col] = make_float4(e0.x, e0.y, e1.x, e1.y);
        e0 = splitf2(o[nt][2] * inv1);
        e1 = splitf2(o[nt][3] * inv1);
        *(float4*)&ob[(size_t)(g + 8) * D_MOD + col] = make_float4(e0.x, e0.y, e1.x, e1.y);
    }
}

// ---------------------------------------------------------------------------
extern "C" void kernel_launch(void* const* d_in, const int* in_sizes, int n_in,
                              void* d_out, int out_size)
{
    const float* x = nullptr;
    const float* w_qkv = nullptr;
    const float* w_out = nullptr;
    for (int i = 0; i < n_in; i++) {
        if (in_sizes[i] == MROWS * D_MOD) x = (const float*)d_in[i];
        else if (in_sizes[i] == D_MOD * 3 * D_MOD) w_qkv = (const float*)d_in[i];
        else if (in_sizes[i] == D_MOD * D_MOD) w_out = (const float*)d_in[i];
    }
    float* out = (float*)d_out;

    float2 *qkvp, *attp, *psx, *pswq, *pswo;
    cudaGetSymbolAddress((void**)&qkvp, g_qkvp);
    cudaGetSymbolAddress((void**)&attp, g_attp);
    cudaGetSymbolAddress((void**)&psx, ps_x);
    cudaGetSymbolAddress((void**)&pswq, ps_wqkv);
    cudaGetSymbolAddress((void**)&pswo, ps_wout);

    const int gemm_smem = 2 * (SA_SZ + SB_SZ) * (int)sizeof(float2);   // 70656
    cudaFuncSetAttribute(gemm_ps, cudaFuncAttributeMaxDynamicSharedMemorySize, gemm_smem);
    const int attn_smem = (256 + 64 + 64) * QS2 * (int)sizeof(float2); // 208896
    cudaFuncSetAttribute(attn_ps, cudaFuncAttributeMaxDynamicSharedMemorySize, attn_smem);

    // 0) pre-split inputs (once per call; elementwise)
    {
        int n4;
        n4 = MROWS * D_MOD / 4;
        presplit<<<(n4 + 255) / 256, 256>>>(x, psx, n4);
        n4 = D_MOD * 3 * D_MOD / 4;
        presplit<<<(n4 + 255) / 256, 256>>>(w_qkv, pswq, n4);
        n4 = D_MOD * D_MOD / 4;
        presplit<<<(n4 + 255) / 256, 256>>>(w_out, pswo, n4);
    }

    // 1) QKV projection -> split-packed qkv (Q cols pre-scaled by 0.125)
    gemm_ps<<<dim3(3 * D_MOD / BN, MROWS / BM), dim3(256), gemm_smem>>>(
        psx, pswq, nullptr, qkvp, MROWS, 3 * D_MOD, D_MOD, D_MOD);

    // 2) Attention -> split-packed output
    attn_ps<<<dim3(S_LEN / 256, B_SZ * H_CNT), dim3(512), attn_smem>>>();

    // 3) Output projection -> plain fp32 result
    gemm_ps<<<dim3(D_MOD / BN, MROWS / BM), dim3(256), gemm_smem>>>(
        attp, pswo, out, nullptr, MROWS, D_MOD, D_MOD, 0);
}

// round 15
// speedup vs baseline: 1.1521x; 1.0798x over previous
#include <cuda_runtime.h>
#include <cstdint>

#define B_SZ 4
#define S_LEN 2048
#define D_MOD 1024
#define H_CNT 16
#define HD 64
#define MROWS (B_SZ * S_LEN)          // 8192

// ---------------------------------------------------------------------------
// Packed (hi,lo) scratch in global memory (allocation-free rule)
// ---------------------------------------------------------------------------
__device__ float2 g_qkvp[(size_t)MROWS * 3 * D_MOD];  // split qkv (Q pre-scaled)
__device__ float2 g_attp[(size_t)MROWS * D_MOD];      // split attention output
__device__ float2 ps_x[(size_t)MROWS * D_MOD];        // split x
__device__ float2 ps_wqkv[(size_t)D_MOD * 3 * D_MOD]; // split w_qkv
__device__ float2 ps_wout[(size_t)D_MOD * D_MOD];     // split w_out

// ---------------------------------------------------------------------------
// tf32 helpers
// ---------------------------------------------------------------------------
__device__ __forceinline__ uint32_t f2tf32(float x) {
    uint32_t r;
    asm("cvt.rna.tf32.f32 %0, %1;" : "=r"(r) : "f"(x));
    return r;
}
__device__ __forceinline__ float2 splitf2(float x) {
    float hi = __uint_as_float(f2tf32(x));
    float lo = __uint_as_float(f2tf32(x - hi));
    return make_float2(hi, lo);
}
__device__ __forceinline__ void mma8s(float* c,
    float a0, float a1, float a2, float a3, float b0, float b1)
{
    asm volatile(
        "mma.sync.aligned.m16n8k8.row.col.f32.tf32.tf32.f32 "
        "{%0,%1,%2,%3}, {%4,%5,%6,%7}, {%8,%9}, {%0,%1,%2,%3};"
        : "+f"(c[0]), "+f"(c[1]), "+f"(c[2]), "+f"(c[3])
        : "r"(__float_as_uint(a0)), "r"(__float_as_uint(a1)),
          "r"(__float_as_uint(a2)), "r"(__float_as_uint(a3)),
          "r"(__float_as_uint(b0)), "r"(__float_as_uint(b1)));
}
// split-tf32 product: c += ahi*bhi + ahi*blo + alo*bhi  (float2 = (hi,lo))
__device__ __forceinline__ void mma3(float* c,
    float2 a0, float2 a1, float2 a2, float2 a3, float2 b0, float2 b1)
{
    mma8s(c, a0.x, a1.x, a2.x, a3.x, b0.x, b1.x);
    mma8s(c, a0.x, a1.x, a2.x, a3.x, b0.y, b1.y);
    mma8s(c, a0.y, a1.y, a2.y, a3.y, b0.x, b1.x);
}

// cp.async helpers (16B)
__device__ __forceinline__ void cpa16(void* sdst, const void* gsrc) {
    uint32_t s = (uint32_t)__cvta_generic_to_shared(sdst);
    asm volatile("cp.async.cg.shared.global [%0], [%1], 16;" :: "r"(s), "l"(gsrc));
}
__device__ __forceinline__ void cpa_commit() {
    asm volatile("cp.async.commit_group;");
}
template <int N>
__device__ __forceinline__ void cpa_wait() {
    asm volatile("cp.async.wait_group %0;" :: "n"(N));
}

// ---------------------------------------------------------------------------
// Prep: elementwise split fp32 -> packed float2
// ---------------------------------------------------------------------------
__global__ void presplit(const float* __restrict__ in, float2* __restrict__ out, int n4)
{
    int i = blockIdx.x * blockDim.x + threadIdx.x;
    if (i >= n4) return;
    float4 v = ((const float4*)in)[i];
    float2 e0 = splitf2(v.x), e1 = splitf2(v.y);
    float2 e2 = splitf2(v.z), e3 = splitf2(v.w);
    float4* o = (float4*)(out + (size_t)i * 4);
    o[0] = make_float4(e0.x, e0.y, e1.x, e1.y);
    o[1] = make_float4(e2.x, e2.y, e3.x, e3.y);
}

// ---------------------------------------------------------------------------
// GEMM on pre-split operands: C = A*B. 128x128x16 tile, 256 thr, 8 warps.
// 3-stage cp.async ring, ONE barrier per k-tile:
//   per iter: wait<1> (own groups) -> bar -> issue(kt+2) -> compute(kt)
// ---------------------------------------------------------------------------
#define BM 128
#define BN 128
#define BK 16
#define AS2 18
#define BS2 132
#define SA_SZ (BM * AS2)
#define SB_SZ (BK * BS2)
#define STG_SZ (SA_SZ + SB_SZ)
#define NSTAGE 3

extern __shared__ float2 gsm[];

__global__ __launch_bounds__(256, 2) void gemm_ps(
    const float2* __restrict__ A, const float2* __restrict__ B,
    float* __restrict__ Cout, float2* __restrict__ Cpack,
    int M, int N, int K, int scale_below)
{
    const int tid = threadIdx.x;
    const int lane = tid & 31, warp = tid >> 5;
    const int wm = warp & 1, wn = warp >> 1;
    const int g = lane >> 2, t = lane & 3;
    const int m0 = blockIdx.y * BM, n0 = blockIdx.x * BN;

    float acc[4][4][4];
    #pragma unroll
    for (int i = 0; i < 4; i++)
        #pragma unroll
        for (int j = 0; j < 4; j++)
            #pragma unroll
            for (int e = 0; e < 4; e++) acc[i][j][e] = 0.0f;

    const int nk = K / BK;

    auto issue_tile = [&](int kt) {
        float2* sA = gsm + (kt % NSTAGE) * STG_SZ;
        float2* sB = sA + SA_SZ;
        int k0 = kt * BK;
        #pragma unroll
        for (int i = 0; i < 4; i++) {
            int c = tid + 256 * i;
            int row = c >> 3, kc = c & 7;
            cpa16(&sA[row * AS2 + 2 * kc],
                  A + (size_t)(m0 + row) * K + k0 + 2 * kc);
        }
        #pragma unroll
        for (int i = 0; i < 4; i++) {
            int c = tid + 256 * i;
            int row = c >> 6, nc = c & 63;
            cpa16(&sB[row * BS2 + 2 * nc],
                  B + (size_t)(k0 + row) * N + n0 + 2 * nc);
        }
        cpa_commit();
    };

    issue_tile(0);
    issue_tile(1);

    for (int kt = 0; kt < nk; kt++) {
        if (kt + 1 < nk) cpa_wait<1>(); else cpa_wait<0>();
        __syncthreads();                 // all threads done with iter kt-1
        if (kt + 2 < nk) issue_tile(kt + 2);   // writes stage (kt-1)%3: safe

        float2* sA = gsm + (kt % NSTAGE) * STG_SZ;
        float2* sB = sA + SA_SZ;

        #pragma unroll
        for (int ks = 0; ks < 2; ks++) {
            const int kb = ks * 8;
            float2 af[4][4], bf[4][2];
            #pragma unroll
            for (int mt = 0; mt < 4; mt++) {
                int mb = wm * 64 + mt * 16;
                af[mt][0] = sA[(mb + g) * AS2 + kb + t];
                af[mt][1] = sA[(mb + g + 8) * AS2 + kb + t];
                af[mt][2] = sA[(mb + g) * AS2 + kb + t + 4];
                af[mt][3] = sA[(mb + g + 8) * AS2 + kb + t + 4];
            }
            #pragma unroll
            for (int nt = 0; nt < 4; nt++) {
                int nb = wn * 32 + nt * 8;
                bf[nt][0] = sB[(kb + t) * BS2 + nb + g];
                bf[nt][1] = sB[(kb + t + 4) * BS2 + nb + g];
            }
            #pragma unroll
            for (int mt = 0; mt < 4; mt++)
                #pragma unroll
                for (int nt = 0; nt < 4; nt++)
                    mma3(acc[mt][nt], af[mt][0], af[mt][1], af[mt][2], af[mt][3],
                         bf[nt][0], bf[nt][1]);
        }
    }

    // epilogue
    const float cs = (n0 < scale_below) ? 0.125f : 1.0f;
    #pragma unroll
    for (int mt = 0; mt < 4; mt++) {
        int row = m0 + wm * 64 + mt * 16 + g;
        #pragma unroll
        for (int nt = 0; nt < 4; nt++) {
            int col = n0 + wn * 32 + nt * 8 + 2 * t;
            if (Cpack) {
                float2 e0 = splitf2(acc[mt][nt][0] * cs);
                float2 e1 = splitf2(acc[mt][nt][1] * cs);
                *(float4*)&Cpack[(size_t)row * N + col] =
                    make_float4(e0.x, e0.y, e1.x, e1.y);
                e0 = splitf2(acc[mt][nt][2] * cs);
                e1 = splitf2(acc[mt][nt][3] * cs);
                *(float4*)&Cpack[(size_t)(row + 8) * N + col] =
                    make_float4(e0.x, e0.y, e1.x, e1.y);
            } else {
                *(float2*)(Cout + (size_t)row * N + col) =
                    make_float2(acc[mt][nt][0], acc[mt][nt][1]);
                *(float2*)(Cout + (size_t)(row + 8) * N + col) =
                    make_float2(acc[mt][nt][2], acc[mt][nt][3]);
            }
        }
    }
}

// ---------------------------------------------------------------------------
// Flash attention on pre-split qkv. Block = (b, h, 128-query tile),
// 256 threads, 8 warps x 16 q rows. K/V tiles: 64 keys, DOUBLE-buffered
// cp.async (2 stages), ONE barrier per k-tile:
//   per iter: wait<0> -> bar -> issue(kt+1) -> compute(kt)
// smem stride QS2=68: sQ 128x68, stage[i] = {sK 64x68, sV 64x68}.
// P stays in registers (C-frag -> A-frag shfl transpose + split).
// ---------------------------------------------------------------------------
#define QS2 68
#define KV_SZ (64 * QS2)

__global__ __launch_bounds__(256, 1) void attn_ps()
{
    extern __shared__ float2 smf2[];
    float2* sQ = smf2;                       // 128*68
    float2* kvbase = sQ + 128 * QS2;         // 2 stages of (sK + sV)

    const int tid = threadIdx.x;
    const int lane = tid & 31, warp = tid >> 5;
    const int g = lane >> 2, t = lane & 3;
    const int b = blockIdx.y >> 4, h = blockIdx.y & 15;
    const int q0 = blockIdx.x * 128;
    const int mq = warp * 16;
    const float2* gq = g_qkvp + (size_t)b * S_LEN * (3 * D_MOD) + h * HD;

    const int nk = S_LEN / 64;

    auto issue_kv = [&](int kt) {
        float2* sK = kvbase + (kt & 1) * (2 * KV_SZ);
        float2* sV = sK + KV_SZ;
        #pragma unroll
        for (int i = 0; i < 8; i++) {
            int c = tid + 256 * i;
            int j = c >> 5, dc = c & 31;
            const float2* src = gq + (size_t)(kt * 64 + j) * (3 * D_MOD) + 2 * dc;
            cpa16(&sK[j * QS2 + 2 * dc], src + D_MOD);
            cpa16(&sV[j * QS2 + 2 * dc], src + 2 * D_MOD);
        }
        cpa_commit();
    };

    // prologue: Q (128 rows x 32 chunks) + KV tile 0 in one group
    #pragma unroll
    for (int i = 0; i < 16; i++) {
        int c = tid + 256 * i;
        int r = c >> 5, dc = c & 31;
        cpa16(&sQ[r * QS2 + 2 * dc],
              gq + (size_t)(q0 + r) * (3 * D_MOD) + 2 * dc);
    }
    {
        float2* sK = kvbase;
        float2* sV = sK + KV_SZ;
        #pragma unroll
        for (int i = 0; i < 8; i++) {
            int c = tid + 256 * i;
            int j = c >> 5, dc = c & 31;
            const float2* src = gq + (size_t)j * (3 * D_MOD) + 2 * dc;
            cpa16(&sK[j * QS2 + 2 * dc], src + D_MOD);
            cpa16(&sV[j * QS2 + 2 * dc], src + 2 * D_MOD);
        }
    }
    cpa_commit();

    float o[8][4];
    #pragma unroll
    for (int i = 0; i < 8; i++)
        #pragma unroll
        for (int e = 0; e < 4; e++) o[i][e] = 0.0f;
    float m0r = -1e30f, m1r = -1e30f, l0 = 0.0f, l1 = 0.0f;

    const int ls1 = (lane & ~3) + (t >> 1);
    const int ls2 = ls1 + 2;
    const bool odd = (t & 1);

    for (int kt = 0; kt < nk; kt++) {
        cpa_wait<0>();           // own copies for tile kt (and Q) done
        __syncthreads();         // everyone's copies visible; iter kt-1 done
        if (kt + 1 < nk) issue_kv(kt + 1);   // writes other stage: safe

        float2* sK = kvbase + (kt & 1) * (2 * KV_SZ);
        float2* sV = sK + KV_SZ;

        // ---- S = Q K^T ----
        float s[8][4];
        #pragma unroll
        for (int i = 0; i < 8; i++)
            #pragma unroll
            for (int e = 0; e < 4; e++) s[i][e] = 0.0f;

        #pragma unroll
        for (int ds = 0; ds < 8; ds++) {
            int kb = ds * 8;
            float2 q0f = sQ[(mq + g) * QS2 + kb + t];
            float2 q1f = sQ[(mq + g + 8) * QS2 + kb + t];
            float2 q2f = sQ[(mq + g) * QS2 + kb + t + 4];
            float2 q3f = sQ[(mq + g + 8) * QS2 + kb + t + 4];
            #pragma unroll
            for (int nt = 0; nt < 8; nt++) {
                float2 k0f = sK[(nt * 8 + g) * QS2 + kb + t];
                float2 k1f = sK[(nt * 8 + g) * QS2 + kb + t + 4];
                mma3(s[nt], q0f, q1f, q2f, q3f, k0f, k1f);
            }
        }

        // ---- online softmax (rows g, g+8) ----
        float mx0 = -1e30f, mx1 = -1e30f;
        #pragma unroll
        for (int nt = 0; nt < 8; nt++) {
            mx0 = fmaxf(mx0, fmaxf(s[nt][0], s[nt][1]));
            mx1 = fmaxf(mx1, fmaxf(s[nt][2], s[nt][3]));
        }
        mx0 = fmaxf(mx0, __shfl_xor_sync(0xffffffffu, mx0, 1));
        mx0 = fmaxf(mx0, __shfl_xor_sync(0xffffffffu, mx0, 2));
        mx1 = fmaxf(mx1, __shfl_xor_sync(0xffffffffu, mx1, 1));
        mx1 = fmaxf(mx1, __shfl_xor_sync(0xffffffffu, mx1, 2));

        float mn0 = fmaxf(m0r, mx0), mn1 = fmaxf(m1r, mx1);
        float f0 = __expf(m0r - mn0), f1 = __expf(m1r - mn1);
        m0r = mn0; m1r = mn1;

        float rs0 = 0.0f, rs1 = 0.0f;
        #pragma unroll
        for (int nt = 0; nt < 8; nt++) {
            s[nt][0] = __expf(s[nt][0] - mn0); rs0 += s[nt][0];
            s[nt][1] = __expf(s[nt][1] - mn0); rs0 += s[nt][1];
            s[nt][2] = __expf(s[nt][2] - mn1); rs1 += s[nt][2];
            s[nt][3] = __expf(s[nt][3] - mn1); rs1 += s[nt][3];
        }
        rs0 += __shfl_xor_sync(0xffffffffu, rs0, 1);
        rs0 += __shfl_xor_sync(0xffffffffu, rs0, 2);
        rs1 += __shfl_xor_sync(0xffffffffu, rs1, 1);
        rs1 += __shfl_xor_sync(0xffffffffu, rs1, 2);
        l0 = l0 * f0 + rs0;
        l1 = l1 * f1 + rs1;
        #pragma unroll
        for (int nt = 0; nt < 8; nt++) {
            o[nt][0] *= f0; o[nt][1] *= f0;
            o[nt][2] *= f1; o[nt][3] *= f1;
        }

        // ---- O += P V ----
        #pragma unroll
        for (int ks = 0; ks < 8; ks++) {
            float p00 = __shfl_sync(0xffffffffu, s[ks][0], ls1);
            float p01 = __shfl_sync(0xffffffffu, s[ks][1], ls1);
            float p10 = __shfl_sync(0xffffffffu, s[ks][2], ls1);
            float p11 = __shfl_sync(0xffffffffu, s[ks][3], ls1);
            float p20 = __shfl_sync(0xffffffffu, s[ks][0], ls2);
            float p21 = __shfl_sync(0xffffffffu, s[ks][1], ls2);
            float p30 = __shfl_sync(0xffffffffu, s[ks][2], ls2);
            float p31 = __shfl_sync(0xffffffffu, s[ks][3], ls2);
            float2 A0 = splitf2(odd ? p01 : p00);
            float2 A1 = splitf2(odd ? p11 : p10);
            float2 A2 = splitf2(odd ? p21 : p20);
            float2 A3 = splitf2(odd ? p31 : p30);
            int kb = ks * 8;
            #pragma unroll
            for (int nt = 0; nt < 8; nt++) {
                float2 v0f = sV[(kb + t) * QS2 + nt * 8 + g];
                float2 v1f = sV[(kb + t + 4) * QS2 + nt * 8 + g];
                mma3(o[nt], A0, A1, A2, A3, v0f, v1f);
            }
        }
    }

    // ---- epilogue: normalize, split, write packed [B*S, D] for GEMM2 ----
    float inv0 = 1.0f / l0, inv1 = 1.0f / l1;
    float2* ob = g_attp + ((size_t)b * S_LEN + q0 + mq) * D_MOD + h * HD;
    #pragma unroll
    for (int nt = 0; nt < 8; nt++) {
        int col = nt * 8 + 2 * t;
        float2 e0 = splitf2(o[nt][0] * inv0);
        float2 e1 = splitf2(o[nt][1] * inv0);
        *(float4*)&ob[(size_t)g * D_MOD + col] = make_float4(e0.x, e0.y, e1.x, e1.y);
        e0 = splitf2(o[nt][2] * inv1);
        e1 = splitf2(o[nt][3] * inv1);
        *(float4*)&ob[(size_t)(g + 8) * D_MOD + col] = make_float4(e0.x, e0.y, e1.x, e1.y);
    }
}

// ---------------------------------------------------------------------------
extern "C" void kernel_launch(void* const* d_in, const int* in_sizes, int n_in,
                              void* d_out, int out_size)
{
    const float* x = nullptr;
    const float* w_qkv = nullptr;
    const float* w_out = nullptr;
    for (int i = 0; i < n_in; i++) {
        if (in_sizes[i] == MROWS * D_MOD) x = (const float*)d_in[i];
        else if (in_sizes[i] == D_MOD * 3 * D_MOD) w_qkv = (const float*)d_in[i];
        else if (in_sizes[i] == D_MOD * D_MOD) w_out = (const float*)d_in[i];
    }
    float* out = (float*)d_out;

    float2 *qkvp, *attp, *psx, *pswq, *pswo;
    cudaGetSymbolAddress((void**)&qkvp, g_qkvp);
    cudaGetSymbolAddress((void**)&attp, g_attp);
    cudaGetSymbolAddress((void**)&psx, ps_x);
    cudaGetSymbolAddress((void**)&pswq, ps_wqkv);
    cudaGetSymbolAddress((void**)&pswo, ps_wout);

    const int gemm_smem = NSTAGE * STG_SZ * (int)sizeof(float2);       // 105984
    cudaFuncSetAttribute(gemm_ps, cudaFuncAttributeMaxDynamicSharedMemorySize, gemm_smem);
    const int attn_smem = (128 + 4 * 64) * QS2 * (int)sizeof(float2);  // 208896
    cudaFuncSetAttribute(attn_ps, cudaFuncAttributeMaxDynamicSharedMemorySize, attn_smem);

    // 0) pre-split inputs
    {
        int n4;
        n4 = MROWS * D_MOD / 4;
        presplit<<<(n4 + 255) / 256, 256>>>(x, psx, n4);
        n4 = D_MOD * 3 * D_MOD / 4;
        presplit<<<(n4 + 255) / 256, 256>>>(w_qkv, pswq, n4);
        n4 = D_MOD * D_MOD / 4;
        presplit<<<(n4 + 255) / 256, 256>>>(w_out, pswo, n4);
    }

    // 1) QKV projection -> split-packed qkv (Q cols pre-scaled by 0.125)
    gemm_ps<<<dim3(3 * D_MOD / BN, MROWS / BM), dim3(256), gemm_smem>>>(
        psx, pswq, nullptr, qkvp, MROWS, 3 * D_MOD, D_MOD, D_MOD);

    // 2) Attention -> split-packed output
    attn_ps<<<dim3(S_LEN / 128, B_SZ * H_CNT), dim3(256), attn_smem>>>();

    // 3) Output projection -> plain fp32 result
    gemm_ps<<<dim3(D_MOD / BN, MROWS / BM), dim3(256), gemm_smem>>>(
        attp, pswo, out, nullptr, MROWS, D_MOD, D_MOD, 0);
}